// round 8
// baseline (speedup 1.0000x reference)
#include <cuda_runtime.h>
#include <math.h>

// Problem constants (fixed by the reference: B=64, P=1024, D=768)
#define Bsz   64
#define Pseq  1024
#define Ddim  768
#define SPLIT 4                        // CTAs per batch -> 256 CTAs total
#define ROWS_PER_CTA (Pseq / SPLIT)    // 256
#define NWARPS 8
#define NTHREADS (NWARPS * 32)         // 256
#define ROWS_PER_WARP (ROWS_PER_CTA / NWARPS)  // 32 (compile-time!)
#define DPL (Ddim / 32)                // 24 d-elements per lane
#define SLOTS (Bsz * SPLIT)            // 256

#define QE  16                         // e-rows per qw-partial chunk
#define QNC (Ddim / QE)                // 48 chunks

// Scratch (no cudaMalloc allowed) -------------------------------------------
__device__ float g_qw_part[QNC][Ddim];
__device__ float g_qw[Ddim];
__device__ float g_pm[SLOTS];
__device__ float g_pl[SLOTS];
__device__ float g_pacc[SLOTS * Ddim];
__device__ int   g_qcnt;               // static-zero; reset after use (graph-safe)

// Kernel 1: partial qw + fused last-CTA reduce (proven in R7) -----------------
__global__ void qw_kernel(const float* __restrict__ q,
                          const float* __restrict__ W) {
    const int d4 = threadIdx.x * 4;
    const int e0 = blockIdx.x * QE;
    float4 acc = make_float4(0.f, 0.f, 0.f, 0.f);
#pragma unroll
    for (int i = 0; i < QE; ++i) {
        const float qv = __ldg(&q[e0 + i]);
        const float4 w = *reinterpret_cast<const float4*>(&W[(long)(e0 + i) * Ddim + d4]);
        acc.x += qv * w.x; acc.y += qv * w.y;
        acc.z += qv * w.z; acc.w += qv * w.w;
    }
    *reinterpret_cast<float4*>(&g_qw_part[blockIdx.x][d4]) = acc;

    __threadfence();
    __shared__ int is_last;
    if (threadIdx.x == 0)
        is_last = (atomicAdd(&g_qcnt, 1) == QNC - 1);
    __syncthreads();

    if (is_last) {
        if (threadIdx.x == 0) g_qcnt = 0;          // reset for next replay
        __threadfence();
        float4 s = make_float4(0.f, 0.f, 0.f, 0.f);
#pragma unroll
        for (int c = 0; c < QNC; ++c) {
            const float4 v = *reinterpret_cast<const float4*>(&g_qw_part[c][d4]);
            s.x += v.x; s.y += v.y; s.z += v.z; s.w += v.w;
        }
        const float sc = rsqrtf((float)Ddim);
        s.x *= sc; s.y *= sc; s.z *= sc; s.w *= sc;
        *reinterpret_cast<float4*>(&g_qw[d4]) = s;
    }
}

// Kernel 2: per-(batch, quarter) online-softmax pooled partial -----------------
// EXACT R6 loop (no fused tail, no fence) + zero-register L2 prefetch of
// rows r+4/r+5 (one 128B-line prefetch per lane covers a full 3KB row).
__device__ __forceinline__ void load_row(const float* __restrict__ zr, int lane,
                                         float v[DPL]) {
#pragma unroll
    for (int i = 0; i < 6; ++i) {
        float4 t = *reinterpret_cast<const float4*>(&zr[i * 128 + lane * 4]);
        v[i * 4 + 0] = t.x; v[i * 4 + 1] = t.y;
        v[i * 4 + 2] = t.z; v[i * 4 + 3] = t.w;
    }
}

extern __shared__ float smem[];
__global__ __launch_bounds__(NTHREADS, 2)
void attn_partial_kernel(const float* __restrict__ z) {
    float* qw_s  = smem;                     // [Ddim]
    float* acc_s = smem + Ddim;              // [NWARPS * Ddim]
    float* m_s   = acc_s + NWARPS * Ddim;    // [NWARPS]
    float* l_s   = m_s + NWARPS;             // [NWARPS]

    const int bid  = blockIdx.x;             // 0..255 ; batch = bid/SPLIT
    const int tid  = threadIdx.x;
    const int w    = tid >> 5;
    const int lane = tid & 31;

    for (int t = tid; t < Ddim; t += NTHREADS) qw_s[t] = g_qw[t];
    __syncthreads();

    float qw_r[DPL];
    load_row(qw_s, lane, qw_r);

    float m = -INFINITY, l = 0.f;
    float acc[DPL];
#pragma unroll
    for (int j = 0; j < DPL; ++j) acc[j] = 0.f;

    const float* zb = z + ((long)bid * ROWS_PER_CTA + (long)w * ROWS_PER_WARP) * Ddim;

    for (int r = 0; r < ROWS_PER_WARP; r += 2) {
        // L2 prefetch two pairs ahead (no registers, no scoreboard)
        if (r + 4 < ROWS_PER_WARP) {
            const char* p0 = (const char*)(zb + (long)(r + 4) * Ddim) + lane * 128;
            const char* p1 = (const char*)(zb + (long)(r + 5) * Ddim) + lane * 128;
            asm volatile("prefetch.global.L2 [%0];" :: "l"(p0));
            asm volatile("prefetch.global.L2 [%0];" :: "l"(p1));
        }

        float cv0[DPL], cv1[DPL];
        load_row(zb + (long)r * Ddim,       lane, cv0);   // 12 LDG.128
        load_row(zb + (long)(r + 1) * Ddim, lane, cv1);   // back-to-back

        float s0 = 0.f, s1 = 0.f;
#pragma unroll
        for (int j = 0; j < DPL; ++j) { s0 += cv0[j] * qw_r[j]; s1 += cv1[j] * qw_r[j]; }
#pragma unroll
        for (int o = 16; o; o >>= 1) {        // two butterflies, interleaved
            s0 += __shfl_xor_sync(0xffffffffu, s0, o);
            s1 += __shfl_xor_sync(0xffffffffu, s1, o);
        }

        float m_new = fmaxf(m, fmaxf(s0, s1));
        float alpha = __expf(m - m_new);      // exp(-inf)=0 first pair: safe
        float w0    = __expf(s0 - m_new);
        float w1    = __expf(s1 - m_new);
        l = l * alpha + w0 + w1;
#pragma unroll
        for (int j = 0; j < DPL; ++j)
            acc[j] = acc[j] * alpha + w0 * cv0[j] + w1 * cv1[j];
        m = m_new;
    }

    // Stage per-warp state to smem
#pragma unroll
    for (int i = 0; i < 6; ++i) {
        float4 v = make_float4(acc[i * 4 + 0], acc[i * 4 + 1],
                               acc[i * 4 + 2], acc[i * 4 + 3]);
        *reinterpret_cast<float4*>(&acc_s[w * Ddim + i * 128 + lane * 4]) = v;
    }
    if (lane == 0) { m_s[w] = m; l_s[w] = l; }
    __syncthreads();

    // Cross-warp combine into one partial per CTA
    float M = -INFINITY;
#pragma unroll
    for (int ww = 0; ww < NWARPS; ++ww) M = fmaxf(M, m_s[ww]);

    float ew[NWARPS];
#pragma unroll
    for (int ww = 0; ww < NWARPS; ++ww) ew[ww] = __expf(m_s[ww] - M);

    for (int t = tid; t < Ddim; t += NTHREADS) {
        float sum = 0.f;
#pragma unroll
        for (int ww = 0; ww < NWARPS; ++ww)
            sum += ew[ww] * acc_s[ww * Ddim + t];
        g_pacc[bid * Ddim + t] = sum;
    }
    if (tid == 0) {
        float L = 0.f;
#pragma unroll
        for (int ww = 0; ww < NWARPS; ++ww) L += ew[ww] * l_s[ww];
        g_pm[bid] = M;
        g_pl[bid] = L;
    }
}

// Kernel 3: merge SPLIT fixed slots per batch. 256 CTAs x 192 threads ----------
__global__ void combine_kernel(float* __restrict__ out) {
    const int b = blockIdx.x >> 2;
    const int t = (blockIdx.x & 3) * 192 + threadIdx.x;

    float ms[SPLIT], ls[SPLIT];
#pragma unroll
    for (int s = 0; s < SPLIT; ++s) {
        ms[s] = g_pm[b * SPLIT + s];
        ls[s] = g_pl[b * SPLIT + s];
    }
    float M = -INFINITY;
#pragma unroll
    for (int s = 0; s < SPLIT; ++s) M = fmaxf(M, ms[s]);

    float L = 0.f, num = 0.f;
#pragma unroll
    for (int s = 0; s < SPLIT; ++s) {
        float e = __expf(ms[s] - M);
        L   += e * ls[s];
        num += e * g_pacc[(b * SPLIT + s) * Ddim + t];
    }
    out[b * Ddim + t] = num / L;
}

// ----------------------------------------------------------------------------
extern "C" void kernel_launch(void* const* d_in, const int* in_sizes, int n_in,
                              void* d_out, int out_size) {
    const float* z = nullptr; const float* q = nullptr; const float* W = nullptr;
    for (int i = 0; i < n_in; ++i) {
        if (in_sizes[i] == Bsz * Pseq * Ddim)      z = (const float*)d_in[i];
        else if (in_sizes[i] == Ddim)              q = (const float*)d_in[i];
        else if (in_sizes[i] == Ddim * Ddim)       W = (const float*)d_in[i];
    }
    float* out = (float*)d_out;

    const int smem_bytes = (Ddim + NWARPS * Ddim + 2 * NWARPS) * (int)sizeof(float);
    cudaFuncSetAttribute(attn_partial_kernel,
                         cudaFuncAttributeMaxDynamicSharedMemorySize, smem_bytes);

    qw_kernel<<<QNC, Ddim / 4>>>(q, W);
    attn_partial_kernel<<<Bsz * SPLIT, NTHREADS, smem_bytes>>>(z);
    combine_kernel<<<Bsz * SPLIT, 192>>>(out);
}

// round 9
// speedup vs baseline: 1.0573x; 1.0573x over previous
#include <cuda_runtime.h>
#include <cooperative_groups.h>
#include <math.h>

namespace cg = cooperative_groups;

// Problem constants (fixed by the reference: B=64, P=1024, D=768)
#define Bsz   64
#define Pseq  1024
#define Ddim  768
#define SPLIT 4                        // CTAs per batch = cluster size
#define ROWS_PER_CTA (Pseq / SPLIT)    // 256
#define NWARPS 8
#define NTHREADS (NWARPS * 32)         // 256
#define ROWS_PER_WARP (ROWS_PER_CTA / NWARPS)  // 32 (compile-time!)
#define DPL (Ddim / 32)                // 24 d-elements per lane
#define DQ  (Ddim / SPLIT)             // 192 outputs per CTA

#define QE  8                          // e-rows per qw-partial chunk
#define QNC (Ddim / QE)                // 96 chunks

// Scratch (no cudaMalloc allowed) -------------------------------------------
__device__ float g_qw_part[QNC][Ddim];
__device__ float g_qw[Ddim];

// Kernel 1a: partial qw. grid=96, block=192; 8 independent LDG.128 per thread.
__global__ void qw_part_kernel(const float* __restrict__ q,
                               const float* __restrict__ W) {
    const int d4 = threadIdx.x * 4;
    const int e0 = blockIdx.x * QE;
    float4 acc = make_float4(0.f, 0.f, 0.f, 0.f);
#pragma unroll
    for (int i = 0; i < QE; ++i) {
        const float qv = __ldg(&q[e0 + i]);
        const float4 w = *reinterpret_cast<const float4*>(&W[(long)(e0 + i) * Ddim + d4]);
        acc.x += qv * w.x; acc.y += qv * w.y;
        acc.z += qv * w.z; acc.w += qv * w.w;
    }
    *reinterpret_cast<float4*>(&g_qw_part[blockIdx.x][d4]) = acc;
}

// Kernel 1b: fold 96 partials (all independent, L2-hot). grid=4, block=192.
__global__ void qw_reduce_kernel() {
    const int d = blockIdx.x * 192 + threadIdx.x;
    float acc = 0.f;
#pragma unroll
    for (int c = 0; c < QNC; ++c) acc += g_qw_part[c][d];
    g_qw[d] = acc * rsqrtf((float)Ddim);
}

// Kernel 2: online-softmax partials + in-cluster combine ----------------------
// 64 clusters of 4 CTAs (one cluster per batch). Main loop identical to the
// proven R6/R8 pairwise loop; the combine happens over DSMEM after
// cluster.sync() instead of a separate kernel.
__device__ __forceinline__ void load_row(const float* __restrict__ zr, int lane,
                                         float v[DPL]) {
#pragma unroll
    for (int i = 0; i < 6; ++i) {
        float4 t = *reinterpret_cast<const float4*>(&zr[i * 128 + lane * 4]);
        v[i * 4 + 0] = t.x; v[i * 4 + 1] = t.y;
        v[i * 4 + 2] = t.z; v[i * 4 + 3] = t.w;
    }
}

extern __shared__ float smem[];
__global__ __launch_bounds__(NTHREADS, 2) __cluster_dims__(SPLIT, 1, 1)
void attn_kernel(const float* __restrict__ z, float* __restrict__ out) {
    float* qw_s  = smem;                     // [Ddim]
    float* acc_s = smem + Ddim;              // [NWARPS * Ddim]
    float* m_s   = acc_s + NWARPS * Ddim;    // [NWARPS]
    float* l_s   = m_s + NWARPS;             // [NWARPS]
    float* accf  = l_s + NWARPS;             // [Ddim]  CTA-combined partial
    float* mlf   = accf + Ddim;              // [2]     CTA m, l

    const int bid  = blockIdx.x;             // 0..255 ; batch = bid/SPLIT
    const int b    = bid / SPLIT;
    const int rank = bid % SPLIT;            // == cluster rank (linear clusters)
    const int tid  = threadIdx.x;
    const int w    = tid >> 5;
    const int lane = tid & 31;

    for (int t = tid; t < Ddim; t += NTHREADS) qw_s[t] = g_qw[t];
    __syncthreads();

    float qw_r[DPL];
    load_row(qw_s, lane, qw_r);

    float m = -INFINITY, l = 0.f;
    float acc[DPL];
#pragma unroll
    for (int j = 0; j < DPL; ++j) acc[j] = 0.f;

    const float* zb = z + ((long)bid * ROWS_PER_CTA + (long)w * ROWS_PER_WARP) * Ddim;

    for (int r = 0; r < ROWS_PER_WARP; r += 2) {
        if (r + 4 < ROWS_PER_WARP) {   // L2 prefetch two pairs ahead (reg-free)
            const char* p0 = (const char*)(zb + (long)(r + 4) * Ddim) + lane * 128;
            const char* p1 = (const char*)(zb + (long)(r + 5) * Ddim) + lane * 128;
            asm volatile("prefetch.global.L2 [%0];" :: "l"(p0));
            asm volatile("prefetch.global.L2 [%0];" :: "l"(p1));
        }

        float cv0[DPL], cv1[DPL];
        load_row(zb + (long)r * Ddim,       lane, cv0);
        load_row(zb + (long)(r + 1) * Ddim, lane, cv1);

        float s0 = 0.f, s1 = 0.f;
#pragma unroll
        for (int j = 0; j < DPL; ++j) { s0 += cv0[j] * qw_r[j]; s1 += cv1[j] * qw_r[j]; }
#pragma unroll
        for (int o = 16; o; o >>= 1) {
            s0 += __shfl_xor_sync(0xffffffffu, s0, o);
            s1 += __shfl_xor_sync(0xffffffffu, s1, o);
        }

        float m_new = fmaxf(m, fmaxf(s0, s1));
        float alpha = __expf(m - m_new);
        float w0    = __expf(s0 - m_new);
        float w1    = __expf(s1 - m_new);
        l = l * alpha + w0 + w1;
#pragma unroll
        for (int j = 0; j < DPL; ++j)
            acc[j] = acc[j] * alpha + w0 * cv0[j] + w1 * cv1[j];
        m = m_new;
    }

    // Stage per-warp state to smem
#pragma unroll
    for (int i = 0; i < 6; ++i) {
        float4 v = make_float4(acc[i * 4 + 0], acc[i * 4 + 1],
                               acc[i * 4 + 2], acc[i * 4 + 3]);
        *reinterpret_cast<float4*>(&acc_s[w * Ddim + i * 128 + lane * 4]) = v;
    }
    if (lane == 0) { m_s[w] = m; l_s[w] = l; }
    __syncthreads();

    // Cross-warp combine into this CTA's smem partial (accf, mlf)
    float M = -INFINITY;
#pragma unroll
    for (int ww = 0; ww < NWARPS; ++ww) M = fmaxf(M, m_s[ww]);

    float ew[NWARPS];
#pragma unroll
    for (int ww = 0; ww < NWARPS; ++ww) ew[ww] = __expf(m_s[ww] - M);

    for (int t = tid; t < Ddim; t += NTHREADS) {
        float sum = 0.f;
#pragma unroll
        for (int ww = 0; ww < NWARPS; ++ww)
            sum += ew[ww] * acc_s[ww * Ddim + t];
        accf[t] = sum;
    }
    if (tid == 0) {
        float L = 0.f;
#pragma unroll
        for (int ww = 0; ww < NWARPS; ++ww) L += ew[ww] * l_s[ww];
        mlf[0] = M;
        mlf[1] = L;
    }

    // ---- in-cluster combine over DSMEM --------------------------------------
    cg::cluster_group cluster = cg::this_cluster();
    cluster.sync();   // release/acquire: siblings' accf/mlf visible

    float ms[SPLIT], ls[SPLIT];
#pragma unroll
    for (int s = 0; s < SPLIT; ++s) {        // fixed order -> deterministic
        const float* pml = cluster.map_shared_rank(mlf, s);
        ms[s] = pml[0]; ls[s] = pml[1];
    }
    float Mf = -INFINITY;
#pragma unroll
    for (int s = 0; s < SPLIT; ++s) Mf = fmaxf(Mf, ms[s]);

    float es[SPLIT];
    float Lf = 0.f;
#pragma unroll
    for (int s = 0; s < SPLIT; ++s) { es[s] = __expf(ms[s] - Mf); Lf += es[s] * ls[s]; }
    const float inv = 1.0f / Lf;

    if (tid < DQ) {                          // CTA rank writes its 192-quarter
        const int t = rank * DQ + tid;
        float num = 0.f;
#pragma unroll
        for (int s = 0; s < SPLIT; ++s) {
            const float* pa = cluster.map_shared_rank(accf, s);
            num += es[s] * pa[t];
        }
        out[b * Ddim + t] = num * inv;
    }

    cluster.sync();   // keep smem alive until all siblings finish reading
}

// ----------------------------------------------------------------------------
extern "C" void kernel_launch(void* const* d_in, const int* in_sizes, int n_in,
                              void* d_out, int out_size) {
    const float* z = nullptr; const float* q = nullptr; const float* W = nullptr;
    for (int i = 0; i < n_in; ++i) {
        if (in_sizes[i] == Bsz * Pseq * Ddim)      z = (const float*)d_in[i];
        else if (in_sizes[i] == Ddim)              q = (const float*)d_in[i];
        else if (in_sizes[i] == Ddim * Ddim)       W = (const float*)d_in[i];
    }
    float* out = (float*)d_out;

    const int smem_bytes =
        (Ddim + NWARPS * Ddim + 2 * NWARPS + Ddim + 2) * (int)sizeof(float);
    cudaFuncSetAttribute(attn_kernel,
                         cudaFuncAttributeMaxDynamicSharedMemorySize, smem_bytes);

    qw_part_kernel<<<QNC, Ddim / 4>>>(q, W);
    qw_reduce_kernel<<<4, 192>>>();
    attn_kernel<<<Bsz * SPLIT, NTHREADS, smem_bytes>>>(z, out);
}

// round 10
// speedup vs baseline: 1.1413x; 1.0795x over previous
#include <cuda_runtime.h>
#include <math.h>

// Problem constants (fixed by the reference: B=64, P=1024, D=768)
#define Bsz   64
#define Pseq  1024
#define Ddim  768
#define SPLIT 4                        // CTAs per batch -> 256 CTAs total
#define ROWS_PER_CTA (Pseq / SPLIT)    // 256
#define NWARPS 8
#define NTHREADS (NWARPS * 32)         // 256
#define ROWS_PER_WARP (ROWS_PER_CTA / NWARPS)  // 32 (compile-time!)
#define DPL (Ddim / 32)                // 24 d-elements per lane
#define SLOTS (Bsz * SPLIT)            // 256

#define QE  8                          // e-rows per qw-partial chunk
#define QNC (Ddim / QE)                // 96 chunks

// Scratch (no cudaMalloc allowed) -------------------------------------------
__device__ float g_qw_part[QNC][Ddim];
__device__ float g_qw[Ddim];
__device__ float g_pm[SLOTS];
__device__ float g_pl[SLOTS];
__device__ float g_pacc[SLOTS * Ddim];

// Kernel 1a: partial qw. grid=96, block=192; 8 independent LDG.128 per thread.
__global__ void qw_part_kernel(const float* __restrict__ q,
                               const float* __restrict__ W) {
    const int d4 = threadIdx.x * 4;
    const int e0 = blockIdx.x * QE;
    float4 acc = make_float4(0.f, 0.f, 0.f, 0.f);
#pragma unroll
    for (int i = 0; i < QE; ++i) {
        const float qv = __ldg(&q[e0 + i]);
        const float4 w = *reinterpret_cast<const float4*>(&W[(long)(e0 + i) * Ddim + d4]);
        acc.x += qv * w.x; acc.y += qv * w.y;
        acc.z += qv * w.z; acc.w += qv * w.w;
    }
    *reinterpret_cast<float4*>(&g_qw_part[blockIdx.x][d4]) = acc;
}

// Kernel 1b: fold 96 partials (independent, L2-hot). grid=4, block=192. PDL.
__global__ void qw_reduce_kernel() {
    cudaGridDependencySynchronize();           // wait for qw_part results
    const int d = blockIdx.x * 192 + threadIdx.x;
    float acc = 0.f;
#pragma unroll
    for (int c = 0; c < QNC; ++c) acc += g_qw_part[c][d];
    g_qw[d] = acc * rsqrtf((float)Ddim);
}

// Kernel 2: per-(batch, quarter) online-softmax pooled partial -----------------
// EXACT R6 main loop. PDL prologue: prefetch this warp's first 8 z-rows to L2
// (independent of qw), THEN griddepsync, then read g_qw.
__device__ __forceinline__ void load_row(const float* __restrict__ zr, int lane,
                                         float v[DPL]) {
#pragma unroll
    for (int i = 0; i < 6; ++i) {
        float4 t = *reinterpret_cast<const float4*>(&zr[i * 128 + lane * 4]);
        v[i * 4 + 0] = t.x; v[i * 4 + 1] = t.y;
        v[i * 4 + 2] = t.z; v[i * 4 + 3] = t.w;
    }
}

extern __shared__ float smem[];
__global__ __launch_bounds__(NTHREADS, 2)
void attn_partial_kernel(const float* __restrict__ z) {
    float* qw_s  = smem;                     // [Ddim]
    float* acc_s = smem + Ddim;              // [NWARPS * Ddim]
    float* m_s   = acc_s + NWARPS * Ddim;    // [NWARPS]
    float* l_s   = m_s + NWARPS;             // [NWARPS]

    const int bid  = blockIdx.x;             // 0..255 ; batch = bid/SPLIT
    const int tid  = threadIdx.x;
    const int w    = tid >> 5;
    const int lane = tid & 31;

    const float* zb = z + ((long)bid * ROWS_PER_CTA + (long)w * ROWS_PER_WARP) * Ddim;

    // Warm L2 with this warp's first 8 rows while qw kernels finish (reg-free).
#pragma unroll
    for (int r = 0; r < 8; ++r) {
        const char* p = (const char*)(zb + (long)r * Ddim) + lane * 128;
        asm volatile("prefetch.global.L2 [%0];" :: "l"(p));
    }

    cudaGridDependencySynchronize();          // qw results now visible

    for (int t = tid; t < Ddim; t += NTHREADS) qw_s[t] = g_qw[t];
    __syncthreads();

    float qw_r[DPL];
    load_row(qw_s, lane, qw_r);

    float m = -INFINITY, l = 0.f;
    float acc[DPL];
#pragma unroll
    for (int j = 0; j < DPL; ++j) acc[j] = 0.f;

    for (int r = 0; r < ROWS_PER_WARP; r += 2) {
        float cv0[DPL], cv1[DPL];
        load_row(zb + (long)r * Ddim,       lane, cv0);   // 12 LDG.128
        load_row(zb + (long)(r + 1) * Ddim, lane, cv1);   // back-to-back

        float s0 = 0.f, s1 = 0.f;
#pragma unroll
        for (int j = 0; j < DPL; ++j) { s0 += cv0[j] * qw_r[j]; s1 += cv1[j] * qw_r[j]; }
#pragma unroll
        for (int o = 16; o; o >>= 1) {        // two butterflies, interleaved
            s0 += __shfl_xor_sync(0xffffffffu, s0, o);
            s1 += __shfl_xor_sync(0xffffffffu, s1, o);
        }

        float m_new = fmaxf(m, fmaxf(s0, s1));
        float alpha = __expf(m - m_new);      // exp(-inf)=0 first pair: safe
        float w0    = __expf(s0 - m_new);
        float w1    = __expf(s1 - m_new);
        l = l * alpha + w0 + w1;
#pragma unroll
        for (int j = 0; j < DPL; ++j)
            acc[j] = acc[j] * alpha + w0 * cv0[j] + w1 * cv1[j];
        m = m_new;
    }

    // Stage per-warp state to smem
#pragma unroll
    for (int i = 0; i < 6; ++i) {
        float4 v = make_float4(acc[i * 4 + 0], acc[i * 4 + 1],
                               acc[i * 4 + 2], acc[i * 4 + 3]);
        *reinterpret_cast<float4*>(&acc_s[w * Ddim + i * 128 + lane * 4]) = v;
    }
    if (lane == 0) { m_s[w] = m; l_s[w] = l; }
    __syncthreads();

    // Cross-warp combine into one partial per CTA
    float M = -INFINITY;
#pragma unroll
    for (int ww = 0; ww < NWARPS; ++ww) M = fmaxf(M, m_s[ww]);

    float ew[NWARPS];
#pragma unroll
    for (int ww = 0; ww < NWARPS; ++ww) ew[ww] = __expf(m_s[ww] - M);

    for (int t = tid; t < Ddim; t += NTHREADS) {
        float sum = 0.f;
#pragma unroll
        for (int ww = 0; ww < NWARPS; ++ww)
            sum += ew[ww] * acc_s[ww * Ddim + t];
        g_pacc[bid * Ddim + t] = sum;
    }
    if (tid == 0) {
        float L = 0.f;
#pragma unroll
        for (int ww = 0; ww < NWARPS; ++ww) L += ew[ww] * l_s[ww];
        g_pm[bid] = M;
        g_pl[bid] = L;
    }
}

// Kernel 3: merge SPLIT fixed slots per batch. 256 CTAs x 192 threads. PDL.
__global__ void combine_kernel(float* __restrict__ out) {
    cudaGridDependencySynchronize();          // all attn partials visible
    const int b = blockIdx.x >> 2;
    const int t = (blockIdx.x & 3) * 192 + threadIdx.x;

    float ms[SPLIT], ls[SPLIT];
#pragma unroll
    for (int s = 0; s < SPLIT; ++s) {
        ms[s] = g_pm[b * SPLIT + s];
        ls[s] = g_pl[b * SPLIT + s];
    }
    float M = -INFINITY;
#pragma unroll
    for (int s = 0; s < SPLIT; ++s) M = fmaxf(M, ms[s]);

    float L = 0.f, num = 0.f;
#pragma unroll
    for (int s = 0; s < SPLIT; ++s) {
        float e = __expf(ms[s] - M);
        L   += e * ls[s];
        num += e * g_pacc[(b * SPLIT + s) * Ddim + t];
    }
    out[b * Ddim + t] = num / L;
}

// ----------------------------------------------------------------------------
template <typename F, typename... Args>
static void launch_pdl(F func, dim3 grid, dim3 block, size_t smem, Args... args) {
    cudaLaunchConfig_t cfg = {};
    cfg.gridDim = grid; cfg.blockDim = block;
    cfg.dynamicSmemBytes = smem; cfg.stream = 0;
    cudaLaunchAttribute attr[1];
    attr[0].id = cudaLaunchAttributeProgrammaticStreamSerialization;
    attr[0].val.programmaticStreamSerializationAllowed = 1;
    cfg.attrs = attr; cfg.numAttrs = 1;
    cudaLaunchKernelEx(&cfg, func, args...);
}

extern "C" void kernel_launch(void* const* d_in, const int* in_sizes, int n_in,
                              void* d_out, int out_size) {
    const float* z = nullptr; const float* q = nullptr; const float* W = nullptr;
    for (int i = 0; i < n_in; ++i) {
        if (in_sizes[i] == Bsz * Pseq * Ddim)      z = (const float*)d_in[i];
        else if (in_sizes[i] == Ddim)              q = (const float*)d_in[i];
        else if (in_sizes[i] == Ddim * Ddim)       W = (const float*)d_in[i];
    }
    float* out = (float*)d_out;

    const int smem_bytes = (Ddim + NWARPS * Ddim + 2 * NWARPS) * (int)sizeof(float);
    cudaFuncSetAttribute(attn_partial_kernel,
                         cudaFuncAttributeMaxDynamicSharedMemorySize, smem_bytes);

    qw_part_kernel<<<QNC, Ddim / 4>>>(q, W);
    launch_pdl(qw_reduce_kernel, dim3(4), dim3(192), 0);
    launch_pdl(attn_partial_kernel, dim3(Bsz * SPLIT), dim3(NTHREADS),
               (size_t)smem_bytes, z);
    launch_pdl(combine_kernel, dim3(Bsz * SPLIT), dim3(192), (size_t)0, out);
}